// round 8
// baseline (speedup 1.0000x reference)
#include <cuda_runtime.h>
#include <math.h>

// Problem constants
#define NROWS 2048
#define DIMW  512
#define NH    8
#define HD    64                       // head dim (D == M == 64)
#define O_SIZE  (NROWS * DIMW)         // 1,048,576
#define SI_SIZE (NROWS * NH * HD * HD) // 67,108,864

// Scratch for projected Q, K, V (post-activation), 12.6 MB total.
// __device__ global array: allowed scratch (no dynamic allocation).
__device__ float g_QKV[3][NROWS * DIMW];

// ---------------------------------------------------------------------------
// Kernel 1: fused QKV projection GEMM (fp32, smem-tiled 128x64x32)
//   C[n][j] = act( sum_k X[n][k] * W[j][k] + b[j] )
//   z=0: Q with elu+1, z=1: K with elu+1, z=2: V raw
// ---------------------------------------------------------------------------
__global__ __launch_bounds__(256) void qkv_gemm_kernel(
    const float* __restrict__ Xq, const float* __restrict__ Xk, const float* __restrict__ Xv,
    const float* __restrict__ Wq, const float* __restrict__ bq,
    const float* __restrict__ Wk, const float* __restrict__ bk,
    const float* __restrict__ Wv, const float* __restrict__ bv)
{
    const int z = blockIdx.z;
    const float* __restrict__ X = (z == 0) ? Xq : ((z == 1) ? Xk : Xv);
    const float* __restrict__ W = (z == 0) ? Wq : ((z == 1) ? Wk : Wv);
    const float* __restrict__ B = (z == 0) ? bq : ((z == 1) ? bk : bv);
    float* __restrict__ C = g_QKV[z];

    // Transposed-in-smem tiles with padding for conflict-free float4 reads.
    __shared__ float A_s[32 * 132];   // [k][m], m-rows padded 128->132
    __shared__ float B_s[32 * 68];    // [k][n], n-rows padded 64->68

    const int m0  = blockIdx.x * 128;
    const int n0  = blockIdx.y * 64;
    const int tid = threadIdx.x;
    const int tx  = tid & 15;         // output col group (4 cols)
    const int ty  = tid >> 4;         // output row group (8 rows)

    float acc[8][4];
    #pragma unroll
    for (int i = 0; i < 8; i++)
        #pragma unroll
        for (int j = 0; j < 4; j++) acc[i][j] = 0.0f;

    for (int ko = 0; ko < DIMW; ko += 32) {
        // Load A tile (128 rows x 32 k) -> A_s[k][m]
        #pragma unroll
        for (int j = 0; j < 4; j++) {
            int f   = tid + 256 * j;        // 0..1023 float4 slots
            int row = f >> 3;               // 0..127
            int kc  = (f & 7) * 4;          // 0,4,...,28
            float4 v = *(const float4*)&X[(m0 + row) * DIMW + ko + kc];
            A_s[(kc + 0) * 132 + row] = v.x;
            A_s[(kc + 1) * 132 + row] = v.y;
            A_s[(kc + 2) * 132 + row] = v.z;
            A_s[(kc + 3) * 132 + row] = v.w;
        }
        // Load B tile (64 rows x 32 k) -> B_s[k][n]
        #pragma unroll
        for (int j = 0; j < 2; j++) {
            int f   = tid + 256 * j;        // 0..511 float4 slots
            int row = f >> 3;               // 0..63
            int kc  = (f & 7) * 4;
            float4 v = *(const float4*)&W[(n0 + row) * DIMW + ko + kc];
            B_s[(kc + 0) * 68 + row] = v.x;
            B_s[(kc + 1) * 68 + row] = v.y;
            B_s[(kc + 2) * 68 + row] = v.z;
            B_s[(kc + 3) * 68 + row] = v.w;
        }
        __syncthreads();

        #pragma unroll
        for (int kk = 0; kk < 32; kk++) {
            float4 a0 = *(const float4*)&A_s[kk * 132 + ty * 8];
            float4 a1 = *(const float4*)&A_s[kk * 132 + ty * 8 + 4];
            float4 bb = *(const float4*)&B_s[kk * 68 + tx * 4];
            float av[8] = {a0.x, a0.y, a0.z, a0.w, a1.x, a1.y, a1.z, a1.w};
            float bv4[4] = {bb.x, bb.y, bb.z, bb.w};
            #pragma unroll
            for (int i = 0; i < 8; i++)
                #pragma unroll
                for (int j = 0; j < 4; j++)
                    acc[i][j] = fmaf(av[i], bv4[j], acc[i][j]);
        }
        __syncthreads();
    }

    // Epilogue: bias + activation + store
    float bias[4];
    #pragma unroll
    for (int j = 0; j < 4; j++) bias[j] = B[n0 + tx * 4 + j];

    #pragma unroll
    for (int i = 0; i < 8; i++) {
        int row = m0 + ty * 8 + i;
        float4 o;
        float v0 = acc[i][0] + bias[0];
        float v1 = acc[i][1] + bias[1];
        float v2 = acc[i][2] + bias[2];
        float v3 = acc[i][3] + bias[3];
        if (z < 2) {  // elu(x)+1: x>0 -> x+1, else exp(x)
            v0 = (v0 > 0.0f) ? v0 + 1.0f : expf(v0);
            v1 = (v1 > 0.0f) ? v1 + 1.0f : expf(v1);
            v2 = (v2 > 0.0f) ? v2 + 1.0f : expf(v2);
            v3 = (v3 > 0.0f) ? v3 + 1.0f : expf(v3);
        }
        o.x = v0; o.y = v1; o.z = v2; o.w = v3;
        *(float4*)&C[row * DIMW + n0 + tx * 4] = o;
    }
}

// ---------------------------------------------------------------------------
// Kernel 2: per-(n,h) state update + readout (memory-bound streaming over Si)
//   Zi_new = Zi + K
//   Si_new = Si + K (x) V
//   Z      = 1/(Q.Zi_new + eps)
//   out    = (Q.Si + (Q.K) V) * Z      [== Q.Si_new * Z]
// One block per (n,h); 128 threads: tid = dg*16 + mg, thread handles
// d in {dg, dg+8, ...} x m4-group mg (float4 over m).
// ---------------------------------------------------------------------------
__global__ __launch_bounds__(128) void recur_stream_kernel(
    const float* __restrict__ Si, const float* __restrict__ Zi, float* __restrict__ out)
{
    const int nh  = blockIdx.x;      // n*8 + h
    const int tid = threadIdx.x;

    __shared__ float Q_s[64], K_s[64], V_s[64], Zn_s[64];
    __shared__ float red[8 * 64];
    __shared__ float sc[2];          // sc[0]=1/(qz+eps), sc[1]=q.k

    float* __restrict__ outO  = out;
    float* __restrict__ outSi = out + O_SIZE;
    float* __restrict__ outZi = out + O_SIZE + SI_SIZE;

    const int vecbase = nh * HD;     // == n*DIMW + h*64 (since DIMW = NH*HD)

    if (tid < 64) {
        float q = g_QKV[0][vecbase + tid];
        float k = g_QKV[1][vecbase + tid];
        float v = g_QKV[2][vecbase + tid];
        Q_s[tid] = q; K_s[tid] = k; V_s[tid] = v;
        float zn = Zi[vecbase + tid] + k;
        Zn_s[tid] = zn;
        outZi[vecbase + tid] = zn;
    }
    __syncthreads();

    if (tid < 32) {
        float pq = Q_s[tid] * Zn_s[tid] + Q_s[tid + 32] * Zn_s[tid + 32];
        float pk = Q_s[tid] * K_s[tid]  + Q_s[tid + 32] * K_s[tid + 32];
        #pragma unroll
        for (int off = 16; off; off >>= 1) {
            pq += __shfl_xor_sync(0xffffffffu, pq, off);
            pk += __shfl_xor_sync(0xffffffffu, pk, off);
        }
        if (tid == 0) { sc[0] = 1.0f / (pq + 1e-6f); sc[1] = pk; }
    }
    __syncthreads();

    const int mg = tid & 15;         // float4 group over m
    const int dg = tid >> 4;         // 0..7
    const float4* __restrict__ Si4 = (const float4*)(Si    + nh * (HD * HD));
    float4* __restrict__       So4 = (float4*)      (outSi + nh * (HD * HD));
    const float4 vv = *(const float4*)&V_s[mg * 4];

    float4 acc = make_float4(0.f, 0.f, 0.f, 0.f);
    #pragma unroll
    for (int r = 0; r < 8; r++) {
        int d = r * 8 + dg;
        float4 s = Si4[d * 16 + mg];
        float kd = K_s[d];
        float qd = Q_s[d];
        float4 sn;
        sn.x = fmaf(kd, vv.x, s.x);
        sn.y = fmaf(kd, vv.y, s.y);
        sn.z = fmaf(kd, vv.z, s.z);
        sn.w = fmaf(kd, vv.w, s.w);
        So4[d * 16 + mg] = sn;
        acc.x = fmaf(qd, s.x, acc.x);
        acc.y = fmaf(qd, s.y, acc.y);
        acc.z = fmaf(qd, s.z, acc.z);
        acc.w = fmaf(qd, s.w, acc.w);
    }

    *(float4*)&red[dg * 64 + mg * 4] = acc;
    __syncthreads();

    if (tid < 64) {
        float o = 0.0f;
        #pragma unroll
        for (int g = 0; g < 8; g++) o += red[g * 64 + tid];
        o = (o + sc[1] * V_s[tid]) * sc[0];
        outO[vecbase + tid] = o;
    }
}

// ---------------------------------------------------------------------------
// Launcher. Inputs (metadata order):
//  0 query [N,512] 1 key [N,512] 2 value [N,512]
//  3 Si [N,8,64,64] 4 Zi [N,8,64]
//  5 Wq [512,512] 6 bq [512] 7 Wk 8 bk 9 Wv 10 bv
// Output: concat(out [N,512], Si_new [N,8,64,64], Zi_new [N,8,64]) fp32
// ---------------------------------------------------------------------------
extern "C" void kernel_launch(void* const* d_in, const int* in_sizes, int n_in,
                              void* d_out, int out_size) {
    (void)in_sizes; (void)n_in; (void)out_size;
    const float* query = (const float*)d_in[0];
    const float* key   = (const float*)d_in[1];
    const float* value = (const float*)d_in[2];
    const float* Si    = (const float*)d_in[3];
    const float* Zi    = (const float*)d_in[4];
    const float* Wq    = (const float*)d_in[5];
    const float* bq    = (const float*)d_in[6];
    const float* Wk    = (const float*)d_in[7];
    const float* bk    = (const float*)d_in[8];
    const float* Wv    = (const float*)d_in[9];
    const float* bv    = (const float*)d_in[10];
    float* out = (float*)d_out;

    dim3 gemm_grid(NROWS / 128, DIMW / 64, 3);
    qkv_gemm_kernel<<<gemm_grid, 256>>>(query, key, value, Wq, bq, Wk, bk, Wv, bv);

    recur_stream_kernel<<<NROWS * NH, 128>>>(Si, Zi, out);
}

// round 15
// speedup vs baseline: 1.3546x; 1.3546x over previous
#include <cuda_runtime.h>
#include <cuda_bf16.h>
#include <math.h>
#include <stdint.h>

// Problem constants
#define NROWS 2048
#define DIMW  512
#define NH    8
#define HD    64
#define O_SIZE  (NROWS * DIMW)
#define SI_SIZE (NROWS * NH * HD * HD)

// Scratch for projected Q, K, V (post-activation)
__device__ float g_QKV[3][NROWS * DIMW];

__device__ __forceinline__ uint32_t smem_u32(const void* p) {
    uint32_t a;
    asm("{ .reg .u64 t; cvta.to.shared.u64 t, %1; cvt.u32.u64 %0, t; }" : "=r"(a) : "l"(p));
    return a;
}
__device__ __forceinline__ void ldsm4(uint32_t* r, uint32_t addr) {
    asm volatile("ldmatrix.sync.aligned.m8n8.x4.shared.b16 {%0,%1,%2,%3}, [%4];"
                 : "=r"(r[0]), "=r"(r[1]), "=r"(r[2]), "=r"(r[3]) : "r"(addr));
}
__device__ __forceinline__ void ldsm2(uint32_t* r, uint32_t addr) {
    asm volatile("ldmatrix.sync.aligned.m8n8.x2.shared.b16 {%0,%1}, [%2];"
                 : "=r"(r[0]), "=r"(r[1]) : "r"(addr));
}
__device__ __forceinline__ void mma_bf16(float* d, const uint32_t* a, const uint32_t* b) {
    asm volatile(
        "mma.sync.aligned.m16n8k16.row.col.f32.bf16.bf16.f32 "
        "{%0,%1,%2,%3}, {%4,%5,%6,%7}, {%8,%9}, {%0,%1,%2,%3};"
        : "+f"(d[0]), "+f"(d[1]), "+f"(d[2]), "+f"(d[3])
        : "r"(a[0]), "r"(a[1]), "r"(a[2]), "r"(a[3]), "r"(b[0]), "r"(b[1]));
}

// fp32 -> bf16 hi/lo split, 4 elements at a time, stored as uint2 (8B)
static __device__ __forceinline__ void split_store4(float4 v, char* hip, char* lop) {
    __nv_bfloat162 h0 = __float22bfloat162_rn(make_float2(v.x, v.y));
    __nv_bfloat162 h1 = __float22bfloat162_rn(make_float2(v.z, v.w));
    float2 hf0 = __bfloat1622float2(h0);
    float2 hf1 = __bfloat1622float2(h1);
    __nv_bfloat162 l0 = __float22bfloat162_rn(make_float2(v.x - hf0.x, v.y - hf0.y));
    __nv_bfloat162 l1 = __float22bfloat162_rn(make_float2(v.z - hf1.x, v.w - hf1.y));
    uint2 hu, lu;
    hu.x = *reinterpret_cast<uint32_t*>(&h0);
    hu.y = *reinterpret_cast<uint32_t*>(&h1);
    lu.x = *reinterpret_cast<uint32_t*>(&l0);
    lu.y = *reinterpret_cast<uint32_t*>(&l1);
    *reinterpret_cast<uint2*>(hip) = hu;
    *reinterpret_cast<uint2*>(lop) = lu;
}

// ---------------------------------------------------------------------------
// Kernel 1: QKV projection via HMMA (mma.sync bf16, 3-term fp32 split)
//   C[m][n] = act( sum_k X[m][k] * W[n][k] + b[n] )
// Tile BM=128 x BN=128, BK=32 fp32 per chunk (16 chunks).
// Smem rows padded to 40 bf16 (80B): stride=20 banks -> ldmatrix conflict-free.
// ---------------------------------------------------------------------------
#define BM 128
#define BN 128
#define BK 32
#define KST 40          // bf16 row stride (80 bytes)
#define KSTB 80

__global__ __launch_bounds__(256) void qkv_mma_kernel(
    const float* __restrict__ Xq, const float* __restrict__ Xk, const float* __restrict__ Xv,
    const float* __restrict__ Wq, const float* __restrict__ bq,
    const float* __restrict__ Wk, const float* __restrict__ bk,
    const float* __restrict__ Wv, const float* __restrict__ bv)
{
    __shared__ __align__(16) __nv_bfloat16 Ah_s[BM * KST];
    __shared__ __align__(16) __nv_bfloat16 Al_s[BM * KST];
    __shared__ __align__(16) __nv_bfloat16 Bh_s[BN * KST];
    __shared__ __align__(16) __nv_bfloat16 Bl_s[BN * KST];

    const int tid = threadIdx.x;
    const int wid = tid >> 5;
    const int lid = tid & 31;
    const int warp_m = wid & 1;        // 2 warp-rows of 64
    const int warp_n = wid >> 1;       // 4 warp-cols of 32

    const int z  = blockIdx.z;
    const int m0 = blockIdx.x * BM;
    const int n0 = blockIdx.y * BN;

    const float* __restrict__ X  = (z == 0) ? Xq : ((z == 1) ? Xk : Xv);
    const float* __restrict__ W  = (z == 0) ? Wq : ((z == 1) ? Wk : Wv);
    const float* __restrict__ Bv = (z == 0) ? bq : ((z == 1) ? bk : bv);
    float* __restrict__ C = g_QKV[z];

    float acc[4][4][4];
    #pragma unroll
    for (int mi = 0; mi < 4; mi++)
        #pragma unroll
        for (int ni = 0; ni < 4; ni++)
            #pragma unroll
            for (int c = 0; c < 4; c++) acc[mi][ni][c] = 0.0f;

    // ldmatrix base addresses (conflict-free by 80B row stride)
    const uint32_t aAh = smem_u32(Ah_s) + (warp_m * 64 + (lid & 15)) * KSTB + ((lid & 16) ? 16 : 0);
    const uint32_t aAl = smem_u32(Al_s) + (warp_m * 64 + (lid & 15)) * KSTB + ((lid & 16) ? 16 : 0);
    const uint32_t aBh = smem_u32(Bh_s) + (warp_n * 32 + (lid & 7)) * KSTB + ((lid & 8) ? 16 : 0);
    const uint32_t aBl = smem_u32(Bl_s) + (warp_n * 32 + (lid & 7)) * KSTB + ((lid & 8) ? 16 : 0);

    for (int ko = 0; ko < DIMW / BK; ko++) {
        // ---- load fp32 tiles + split-convert to bf16 hi/lo in smem
        const float* Xb = X + (size_t)m0 * DIMW + ko * BK;
        const float* Wb = W + (size_t)n0 * DIMW + ko * BK;
        #pragma unroll
        for (int it = 0; it < 4; it++) {
            int f   = tid + it * 256;          // 0..1023 float4 slots
            int row = f >> 3;                  // 0..127
            int c4  = f & 7;                   // 0..7 (float4 within 32 k)
            float4 va = *(const float4*)(Xb + row * DIMW + c4 * 4);
            split_store4(va, (char*)Ah_s + row * KSTB + c4 * 8,
                             (char*)Al_s + row * KSTB + c4 * 8);
            float4 vb = *(const float4*)(Wb + row * DIMW + c4 * 4);
            split_store4(vb, (char*)Bh_s + row * KSTB + c4 * 8,
                             (char*)Bl_s + row * KSTB + c4 * 8);
        }
        __syncthreads();

        // ---- 2 k-steps of 16, 3 split terms each
        #pragma unroll
        for (int ks = 0; ks < 2; ks++) {
            uint32_t Ah[4][4], Al[4][4], Bh[4][2], Bl[4][2];
            #pragma unroll
            for (int mi = 0; mi < 4; mi++) {
                ldsm4(Ah[mi], aAh + mi * 16 * KSTB + ks * 32);
                ldsm4(Al[mi], aAl + mi * 16 * KSTB + ks * 32);
            }
            #pragma unroll
            for (int ni = 0; ni < 4; ni++) {
                ldsm2(Bh[ni], aBh + ni * 8 * KSTB + ks * 32);
                ldsm2(Bl[ni], aBl + ni * 8 * KSTB + ks * 32);
            }
            #pragma unroll
            for (int mi = 0; mi < 4; mi++)
                #pragma unroll
                for (int ni = 0; ni < 4; ni++) {
                    mma_bf16(acc[mi][ni], Ah[mi], Bh[ni]);
                    mma_bf16(acc[mi][ni], Ah[mi], Bl[ni]);
                    mma_bf16(acc[mi][ni], Al[mi], Bh[ni]);
                }
        }
        __syncthreads();
    }

    // ---- epilogue: bias + activation, direct stores (32B sectors per frag row)
    const int mrow = m0 + warp_m * 64 + (lid >> 2);
    const int ncol = n0 + warp_n * 32 + (lid & 3) * 2;
    #pragma unroll
    for (int ni = 0; ni < 4; ni++) {
        float2 bb = *(const float2*)&Bv[ncol + ni * 8];
        #pragma unroll
        for (int mi = 0; mi < 4; mi++) {
            #pragma unroll
            for (int half = 0; half < 2; half++) {
                float v0 = acc[mi][ni][half * 2 + 0] + bb.x;
                float v1 = acc[mi][ni][half * 2 + 1] + bb.y;
                if (z < 2) {
                    v0 = (v0 > 0.0f) ? v0 + 1.0f : expf(v0);
                    v1 = (v1 > 0.0f) ? v1 + 1.0f : expf(v1);
                }
                int row = mrow + mi * 16 + half * 8;
                *(float2*)&C[(size_t)row * DIMW + ncol + ni * 8] = make_float2(v0, v1);
            }
        }
    }
}

// ---------------------------------------------------------------------------
// Kernel 2: per-(n,h) state update + readout (memory-bound streaming over Si)
//   Zi_new = Zi + K;  Si_new = Si + K(x)V
//   out = (Q.Si + (Q.K) V) / (Q.Zi_new + eps)
// ---------------------------------------------------------------------------
__global__ __launch_bounds__(128) void recur_stream_kernel(
    const float* __restrict__ Si, const float* __restrict__ Zi, float* __restrict__ out)
{
    const int nh  = blockIdx.x;
    const int tid = threadIdx.x;

    __shared__ float Q_s[64], K_s[64], V_s[64], Zn_s[64];
    __shared__ float red[8 * 64];
    __shared__ float sc[2];

    float* __restrict__ outO  = out;
    float* __restrict__ outSi = out + O_SIZE;
    float* __restrict__ outZi = out + O_SIZE + SI_SIZE;

    const int vecbase = nh * HD;

    if (tid < 64) {
        float q = g_QKV[0][vecbase + tid];
        float k = g_QKV[1][vecbase + tid];
        float v = g_QKV[2][vecbase + tid];
        Q_s[tid] = q; K_s[tid] = k; V_s[tid] = v;
        float zn = Zi[vecbase + tid] + k;
        Zn_s[tid] = zn;
        outZi[vecbase + tid] = zn;
    }
    __syncthreads();

    if (tid < 32) {
        float pq = Q_s[tid] * Zn_s[tid] + Q_s[tid + 32] * Zn_s[tid + 32];
        float pk = Q_s[tid] * K_s[tid]  + Q_s[tid + 32] * K_s[tid + 32];
        #pragma unroll
        for (int off = 16; off; off >>= 1) {
            pq += __shfl_xor_sync(0xffffffffu, pq, off);
            pk += __shfl_xor_sync(0xffffffffu, pk, off);
        }
        if (tid == 0) { sc[0] = 1.0f / (pq + 1e-6f); sc[1] = pk; }
    }
    __syncthreads();

    const int mg = tid & 15;
    const int dg = tid >> 4;
    const float4* __restrict__ Si4 = (const float4*)(Si    + (size_t)nh * (HD * HD));
    float4* __restrict__       So4 = (float4*)      (outSi + (size_t)nh * (HD * HD));
    const float4 vv = *(const float4*)&V_s[mg * 4];

    // Batch all 8 Si loads first (MLP=8), streaming hint (no L2 reuse)
    float4 s[8];
    #pragma unroll
    for (int r = 0; r < 8; r++)
        s[r] = __ldcs(&Si4[(r * 8 + dg) * 16 + mg]);

    float4 a = make_float4(0.f, 0.f, 0.f, 0.f);
    #pragma unroll
    for (int r = 0; r < 8; r++) {
        int d = r * 8 + dg;
        float kd = K_s[d];
        float qd = Q_s[d];
        float4 sn;
        sn.x = fmaf(kd, vv.x, s[r].x);
        sn.y = fmaf(kd, vv.y, s[r].y);
        sn.z = fmaf(kd, vv.z, s[r].z);
        sn.w = fmaf(kd, vv.w, s[r].w);
        __stcs(&So4[d * 16 + mg], sn);
        a.x = fmaf(qd, s[r].x, a.x);
        a.y = fmaf(qd, s[r].y, a.y);
        a.z = fmaf(qd, s[r].z, a.z);
        a.w = fmaf(qd, s[r].w, a.w);
    }

    *(float4*)&red[dg * 64 + mg * 4] = a;
    __syncthreads();

    if (tid < 64) {
        float o = 0.0f;
        #pragma unroll
        for (int g = 0; g < 8; g++) o += red[g * 64 + tid];
        o = (o + sc[1] * V_s[tid]) * sc[0];
        outO[vecbase + tid] = o;
    }
}

// ---------------------------------------------------------------------------
// Launcher
// ---------------------------------------------------------------------------
extern "C" void kernel_launch(void* const* d_in, const int* in_sizes, int n_in,
                              void* d_out, int out_size) {
    (void)in_sizes; (void)n_in; (void)out_size;
    const float* query = (const float*)d_in[0];
    const float* key   = (const float*)d_in[1];
    const float* value = (const float*)d_in[2];
    const float* Si    = (const float*)d_in[3];
    const float* Zi    = (const float*)d_in[4];
    const float* Wq    = (const float*)d_in[5];
    const float* bq    = (const float*)d_in[6];
    const float* Wk    = (const float*)d_in[7];
    const float* bk    = (const float*)d_in[8];
    const float* Wv    = (const float*)d_in[9];
    const float* bv    = (const float*)d_in[10];
    float* out = (float*)d_out;

    dim3 grid(NROWS / BM, DIMW / BN, 3);
    qkv_mma_kernel<<<grid, 256>>>(query, key, value, Wq, bq, Wk, bk, Wv, bv);

    recur_stream_kernel<<<NROWS * NH, 128>>>(Si, Zi, out);
}